// round 13
// baseline (speedup 1.0000x reference)
#include <cuda_runtime.h>
#include <cuda_bf16.h>
#include <cstdint>
#include <math.h>

#define BATCH 256
#define CH    64
#define MDIM  4096
#define NT    256
#define S1G   4
#define T1G   ((MDIM/S1G)/64)   // 16 tiles per gram CTA
#define S2A   8
#define T2A   ((MDIM/S2A)/64)   // 8 tiles per apply CTA
#define LDB   72                // bf16 elements per smem row
#define RB    144               // row bytes
#define LDC   65
#define LDW   65

__device__ float g_gram[(size_t)BATCH*S1G*CH*CH];
__device__ float g_sums[BATCH*S1G*CH];
__device__ float g_W[(size_t)BATCH*CH*CH];
__device__ float g_mu[BATCH*CH];

__device__ __forceinline__ uint32_t smem_u32(const void* p) {
    uint32_t a;
    asm("{ .reg .u64 t; cvta.to.shared.u64 t, %1; cvt.u32.u64 %0, t; }" : "=r"(a) : "l"(p));
    return a;
}
#define STS64V2(a,r0,r1) asm volatile("st.shared.v2.b32 [%0], {%1,%2};" :: "r"(a), "r"(r0), "r"(r1) : "memory")
#define CVT_BF2(res,flo,fhi) asm("cvt.rn.satfinite.bf16x2.f32 %0, %1, %2;" : "=r"(res) : "f"(fhi), "f"(flo))

// standard split: x = hi + lo
__device__ __forceinline__ void split_pair(float f0, float f1, uint32_t& uh, uint32_t& ul) {
    CVT_BF2(uh, f0, f1);
    float h0 = __uint_as_float(uh << 16);
    float h1 = __uint_as_float(uh & 0xffff0000u);
    CVT_BF2(ul, f0 - h0, f1 - h1);
}
// gram split: hi and 2*lo (exact doubling in bf16)
__device__ __forceinline__ void split_pair2(float f0, float f1, uint32_t& uh, uint32_t& ul) {
    CVT_BF2(uh, f0, f1);
    float h0 = __uint_as_float(uh << 16);
    float h1 = __uint_as_float(uh & 0xffff0000u);
    CVT_BF2(ul, 2.f * (f0 - h0), 2.f * (f1 - h1));
}
__device__ __forceinline__ void ldm_x4(uint32_t* r, uint32_t addr) {
    asm volatile("ldmatrix.sync.aligned.m8n8.x4.shared.b16 {%0,%1,%2,%3}, [%4];"
                 : "=r"(r[0]), "=r"(r[1]), "=r"(r[2]), "=r"(r[3]) : "r"(addr));
}
__device__ __forceinline__ void ldm_x4t(uint32_t* r, uint32_t addr) {
    asm volatile("ldmatrix.sync.aligned.m8n8.x4.trans.shared.b16 {%0,%1,%2,%3}, [%4];"
                 : "=r"(r[0]), "=r"(r[1]), "=r"(r[2]), "=r"(r[3]) : "r"(addr));
}
__device__ __forceinline__ void mma16816(float* d, const uint32_t* a, uint32_t b0, uint32_t b1) {
    asm volatile("mma.sync.aligned.m16n8k16.row.col.f32.bf16.bf16.f32 "
                 "{%0,%1,%2,%3}, {%4,%5,%6,%7}, {%8,%9}, {%0,%1,%2,%3};"
                 : "+f"(d[0]), "+f"(d[1]), "+f"(d[2]), "+f"(d[3])
                 : "r"(a[0]), "r"(a[1]), "r"(a[2]), "r"(a[3]), "r"(b0), "r"(b1));
}

// =============== Kernel 1: partial P = Xh Xh^T + Xh (2Xl)^T (pipelined, single buffer) ===============
__global__ __launch_bounds__(NT, 5)
void gram_kernel(const float* __restrict__ x)
{
    __shared__ __align__(16) __nv_bfloat16 sh[CH*LDB];
    __shared__ __align__(16) __nv_bfloat16 sl[CH*LDB];
    __shared__ float sp[NT];

    const int b = blockIdx.x, s = blockIdx.y, tid = threadIdx.x;
    const float* xb = x + (size_t)b * CH * MDIM + (size_t)s * (MDIM / S1G);
    const uint32_t hb = smem_u32(sh), lb = smem_u32(sl);

    const int c = tid >> 2, q = tid & 3;
    const int w = tid >> 5, lane = tid & 31;
    const int r0 = (w >> 1) * 16, c0 = (w & 1) * 32;
    const int grp = lane >> 3, li = lane & 7;

    const uint32_t aoff = (uint32_t)(r0 + li + (grp & 1) * 8) * RB + (uint32_t)((grp >> 1) * 8) * 2;
    const uint32_t boff = (uint32_t)(c0 + li + (grp >> 1) * 8) * RB + (uint32_t)((grp & 1) * 8) * 2;

    float D[4][4] = {};
    float ssum = 0.f;

    float4 stage[4];
    {
        const float4* src = (const float4*)(xb + (size_t)c * MDIM);
#pragma unroll
        for (int j = 0; j < 4; ++j) stage[j] = src[q + 4 * j];
    }

    for (int t = 0; t < T1G; ++t) {
        // convert + store staged tile
#pragma unroll
        for (int j = 0; j < 4; ++j) {
            float4 v = stage[j];
            ssum += (v.x + v.y) + (v.z + v.w);
            uint32_t h0, l0, h1, l1;
            split_pair2(v.x, v.y, h0, l0);
            split_pair2(v.z, v.w, h1, l1);
            uint32_t off = (uint32_t)c * RB + (uint32_t)(q + 4 * j) * 8;
            STS64V2(hb + off, h0, h1);
            STS64V2(lb + off, l0, l1);
        }
        __syncthreads();

        // prefetch next tile (LDG latency overlaps MMA block below)
        if (t + 1 < T1G) {
            const float4* src = (const float4*)(xb + (size_t)c * MDIM + (t + 1) * 64);
#pragma unroll
            for (int j = 0; j < 4; ++j) stage[j] = src[q + 4 * j];
        }

#pragma unroll
        for (int kc = 0; kc < 4; ++kc) {
            const uint32_t ka = (uint32_t)kc * 32;
            uint32_t ah[4], bh0[4], bh1[4], bl0[4], bl1[4];
            ldm_x4(ah, hb + aoff + ka);
            ldm_x4(bh0, hb + boff + ka);
            ldm_x4(bh1, hb + boff + ka + 16 * RB);
            ldm_x4(bl0, lb + boff + ka);
            ldm_x4(bl1, lb + boff + ka + 16 * RB);
            mma16816(D[0], ah, bh0[0], bh0[1]);
            mma16816(D[1], ah, bh0[2], bh0[3]);
            mma16816(D[2], ah, bh1[0], bh1[1]);
            mma16816(D[3], ah, bh1[2], bh1[3]);
            mma16816(D[0], ah, bl0[0], bl0[1]);
            mma16816(D[1], ah, bl0[2], bl0[3]);
            mma16816(D[2], ah, bl1[0], bl1[1]);
            mma16816(D[3], ah, bl1[2], bl1[3]);
        }
        __syncthreads();
    }

    sp[tid] = ssum;
    __syncthreads();
    if (tid < CH)
        g_sums[(b * S1G + s) * CH + tid] =
            ((sp[tid * 4] + sp[tid * 4 + 1]) + sp[tid * 4 + 2]) + sp[tid * 4 + 3];

    float* gg = g_gram + (size_t)(b * S1G + s) * CH * CH;
    const int row = r0 + (lane >> 2);
    const int col = c0 + (lane & 3) * 2;
#pragma unroll
    for (int nb = 0; nb < 4; ++nb) {
        *(float2*)(gg + (size_t)row * CH + col + nb * 8)       = make_float2(D[nb][0], D[nb][1]);
        *(float2*)(gg + (size_t)(row + 8) * CH + col + nb * 8) = make_float2(D[nb][2], D[nb][3]);
    }
}

// =============== Kernel 2: reduce (symmetrize) + shrinkage + Cholesky + inverse ===============
#define A_(i,j) covb[(63-(i))*LDC + (63-(j))]

__global__ __launch_bounds__(NT)
void chol_kernel()
{
    __shared__ float covb[CH*LDC];
    __shared__ float Wt[CH*LDW];
    __shared__ float s_mu[CH];
    __shared__ float s_invd[CH];
    __shared__ float s_w[8][2];
    __shared__ float s_bc[2];

    const int b = blockIdx.x, tid = threadIdx.x;

    if (tid < CH) {
        float m = 0.f;
#pragma unroll
        for (int s = 0; s < S1G; s++) m += g_sums[(b * S1G + s) * CH + tid];
        s_mu[tid] = m * (1.f / MDIM);
    }
    __syncthreads();

    for (int idx = tid; idx < CH * CH; idx += NT) {
        int i = idx >> 6, j = idx & 63;
        if (i <= j) {
            float g = 0.f;
#pragma unroll
            for (int p = 0; p < S1G; p++) {
                const float* P = g_gram + ((size_t)(b * S1G + p)) * (CH * CH);
                g += 0.5f * (P[i * CH + j] + P[j * CH + i]);
            }
            float v = g * (1.f / MDIM) - s_mu[i] * s_mu[j];
            covb[i * LDC + j] = v;
            covb[j * LDC + i] = v;
        }
    }
    __syncthreads();

    float tr_p = 0.f, fr_p = 0.f;
    for (int idx = tid; idx < CH * CH; idx += NT) {
        int i = idx >> 6, j = idx & 63;
        float v = covb[i * LDC + j];
        fr_p += v * v;
        if (i == j) tr_p += v;
    }
#pragma unroll
    for (int o = 16; o; o >>= 1) {
        tr_p += __shfl_down_sync(0xffffffffu, tr_p, o);
        fr_p += __shfl_down_sync(0xffffffffu, fr_p, o);
    }
    if ((tid & 31) == 0) { s_w[tid >> 5][0] = tr_p; s_w[tid >> 5][1] = fr_p; }
    __syncthreads();
    if (tid == 0) {
        float tr = 0.f, st = 0.f;
#pragma unroll
        for (int w = 0; w < 8; w++) { tr += s_w[w][0]; st += s_w[w][1]; }
        const float n = (float)MDIM, p = (float)CH;
        float num = (n - 2.f) / n * st + tr * tr;
        float den = (n + 2.f) * (st - tr * tr / p);
        float rho = fminf(num / den, 1.f);
        s_bc[0] = rho;
        s_bc[1] = rho * tr / p;
    }
    __syncthreads();
    {
        const float rho = s_bc[0], dadd = s_bc[1];
        for (int idx = tid; idx < CH * CH; idx += NT) {
            int i = idx >> 6, j = idx & 63;
            float v = covb[i * LDC + j] * (1.f - rho);
            if (i == j) v += dadd;
            covb[i * LDC + j] = v;
        }
    }

    for (int k = 0; k < CH; ++k) {
        __syncthreads();
        if (tid == 0) {
            float d = A_(k, k);
            float sd = sqrtf(d);
            A_(k, k) = sd;
            s_bc[0] = 1.f / sd;
        }
        __syncthreads();
        if (tid > k && tid < CH) A_(tid, k) *= s_bc[0];
        __syncthreads();
        {
            int ii = tid & 63, g = tid >> 6;
            int i = k + 1 + ii;
            if (i < CH) {
                float aik = A_(i, k);
                for (int j = k + 1 + g; j <= i; j += 4)
                    A_(i, j) -= aik * A_(j, k);
            }
        }
    }
    __syncthreads();

    if (tid < CH) s_invd[tid] = 1.f / covb[tid * LDC + tid];
    for (int idx = tid; idx < CH * LDW; idx += NT) Wt[idx] = 0.f;
    __syncthreads();

    if (tid < CH) {
        const int j = tid;
        Wt[j * LDW + j] = s_invd[j];
        for (int i = j - 1; i >= 0; --i) {
            float a = 0.f;
            for (int k = i + 1; k <= j; ++k)
                a += covb[i * LDC + k] * Wt[j * LDW + k];
            Wt[j * LDW + i] = -a * s_invd[i];
        }
    }
    __syncthreads();

    // store W row-major: g_W[c][d] = W[c][d] = Wt[d][c]
    for (int idx = tid; idx < CH * CH; idx += NT) {
        int cc = idx >> 6, d = idx & 63;
        g_W[(size_t)b * CH * CH + idx] = Wt[d * LDW + cc];
    }
    if (tid < CH) g_mu[b * CH + tid] = s_mu[tid];
}

// =============== Kernel 3: Z = W (x - mu) via HMMA bf16 split (pipelined) ===============
__global__ __launch_bounds__(NT)
void apply_kernel(const float* __restrict__ x, float* __restrict__ z)
{
    __shared__ __align__(16) __nv_bfloat16 wh[CH*LDB];
    __shared__ __align__(16) __nv_bfloat16 wl[CH*LDB];
    __shared__ __align__(16) __nv_bfloat16 xh[CH*LDB];
    __shared__ __align__(16) __nv_bfloat16 xl[CH*LDB];

    const int b = blockIdx.x, s = blockIdx.y, tid = threadIdx.x;
    const float* xb = x + (size_t)b * CH * MDIM;
    float*       zb = z + (size_t)b * CH * MDIM;
    const uint32_t whb = smem_u32(wh), wlb = smem_u32(wl);
    const uint32_t xhb = smem_u32(xh), xlb = smem_u32(xl);

    const int c = tid >> 2, q = tid & 3;
    const int w = tid >> 5, lane = tid & 31;
    const int r0 = (w >> 1) * 16, m0 = (w & 1) * 32;
    const int grp = lane >> 3, li = lane & 7;

    const float mu_c = g_mu[b * CH + c];

    // load + split W (row-major [c][d])
    {
        const float4* wsrc = (const float4*)(g_W + (size_t)b * CH * CH + (size_t)c * CH);
#pragma unroll
        for (int j = 0; j < 4; ++j) {
            float4 v = wsrc[q + 4 * j];
            uint32_t h0, l0, h1, l1;
            split_pair(v.x, v.y, h0, l0);
            split_pair(v.z, v.w, h1, l1);
            uint32_t off = (uint32_t)c * RB + (uint32_t)(q + 4 * j) * 8;
            STS64V2(whb + off, h0, h1);
            STS64V2(wlb + off, l0, l1);
        }
    }

    // prefetch first x tile while W settles
    float4 stage[4];
    {
        const float4* src = (const float4*)(xb + (size_t)c * MDIM + s * (T2A * 64));
#pragma unroll
        for (int j = 0; j < 4; ++j) stage[j] = src[q + 4 * j];
    }
    __syncthreads();

    // preload W fragments (reused for all tiles)
    uint32_t wah[4][4], wal[4][4];
    {
        const uint32_t aoff = (uint32_t)(r0 + li + (grp & 1) * 8) * RB + (uint32_t)((grp >> 1) * 8) * 2;
#pragma unroll
        for (int kc = 0; kc < 4; ++kc) {
            ldm_x4(wah[kc], whb + aoff + kc * 32);
            ldm_x4(wal[kc], wlb + aoff + kc * 32);
        }
    }

    const uint32_t boff = (uint32_t)(li + (grp & 1) * 8) * RB + (uint32_t)(m0 + (grp >> 1) * 8) * 2;

    for (int t = 0; t < T2A; ++t) {
        const int mg0 = s * (T2A * 64) + t * 64;
#pragma unroll
        for (int j = 0; j < 4; ++j) {
            float4 v = stage[j];
            v.x -= mu_c; v.y -= mu_c; v.z -= mu_c; v.w -= mu_c;
            uint32_t h0, l0, h1, l1;
            split_pair(v.x, v.y, h0, l0);
            split_pair(v.z, v.w, h1, l1);
            uint32_t off = (uint32_t)c * RB + (uint32_t)(q + 4 * j) * 8;
            STS64V2(xhb + off, h0, h1);
            STS64V2(xlb + off, l0, l1);
        }
        __syncthreads();

        if (t + 1 < T2A) {
            const float4* src = (const float4*)(xb + (size_t)c * MDIM + mg0 + 64);
#pragma unroll
            for (int j = 0; j < 4; ++j) stage[j] = src[q + 4 * j];
        }

        float D[4][4] = {};
#pragma unroll
        for (int kc = 0; kc < 4; ++kc) {
            const uint32_t kb = (uint32_t)(kc * 16) * RB;
            uint32_t bh0[4], bh1[4], bl0[4], bl1[4];
            ldm_x4t(bh0, xhb + boff + kb);
            ldm_x4t(bh1, xhb + boff + kb + 32);
            ldm_x4t(bl0, xlb + boff + kb);
            ldm_x4t(bl1, xlb + boff + kb + 32);
            mma16816(D[0], wah[kc], bh0[0], bh0[1]);
            mma16816(D[0], wah[kc], bl0[0], bl0[1]);
            mma16816(D[0], wal[kc], bh0[0], bh0[1]);
            mma16816(D[1], wah[kc], bh0[2], bh0[3]);
            mma16816(D[1], wah[kc], bl0[2], bl0[3]);
            mma16816(D[1], wal[kc], bh0[2], bh0[3]);
            mma16816(D[2], wah[kc], bh1[0], bh1[1]);
            mma16816(D[2], wah[kc], bl1[0], bl1[1]);
            mma16816(D[2], wal[kc], bh1[0], bh1[1]);
            mma16816(D[3], wah[kc], bh1[2], bh1[3]);
            mma16816(D[3], wah[kc], bl1[2], bl1[3]);
            mma16816(D[3], wal[kc], bh1[2], bh1[3]);
        }

        const int row = r0 + (lane >> 2);
        const int mg = mg0 + m0 + (lane & 3) * 2;
#pragma unroll
        for (int nb = 0; nb < 4; ++nb) {
            *(float2*)(zb + (size_t)row * MDIM + mg + nb * 8)       = make_float2(D[nb][0], D[nb][1]);
            *(float2*)(zb + (size_t)(row + 8) * MDIM + mg + nb * 8) = make_float2(D[nb][2], D[nb][3]);
        }
        __syncthreads();
    }
}

extern "C" void kernel_launch(void* const* d_in, const int* in_sizes, int n_in,
                              void* d_out, int out_size)
{
    const float* x = (const float*)d_in[0];
    float* z = (float*)d_out;

    gram_kernel<<<dim3(BATCH, S1G), NT>>>(x);
    chol_kernel<<<BATCH, NT>>>();
    apply_kernel<<<dim3(BATCH, S2A), NT>>>(x, z);
}

// round 14
// speedup vs baseline: 1.1160x; 1.1160x over previous
#include <cuda_runtime.h>
#include <cuda_bf16.h>
#include <cstdint>
#include <math.h>

#define BATCH 256
#define CH    64
#define MDIM  4096
#define NT    256
#define S1G   4
#define T1G   ((MDIM/S1G)/64)   // 16 tiles per gram CTA
#define S2A   8
#define T2A   ((MDIM/S2A)/64)   // 8 tiles per apply CTA
#define LDB   72                // bf16 elements per smem row
#define RB    144               // row bytes
#define LDC   65
#define LDW   65

__device__ float g_gram[(size_t)BATCH*S1G*CH*CH];
__device__ float g_sums[BATCH*S1G*CH];
__device__ float g_W[(size_t)BATCH*CH*CH];
__device__ float g_mu[BATCH*CH];

__device__ __forceinline__ uint32_t smem_u32(const void* p) {
    uint32_t a;
    asm("{ .reg .u64 t; cvta.to.shared.u64 t, %1; cvt.u32.u64 %0, t; }" : "=r"(a) : "l"(p));
    return a;
}
#define STS64V2(a,r0,r1) asm volatile("st.shared.v2.b32 [%0], {%1,%2};" :: "r"(a), "r"(r0), "r"(r1) : "memory")
#define CVT_BF2(res,flo,fhi) asm("cvt.rn.satfinite.bf16x2.f32 %0, %1, %2;" : "=r"(res) : "f"(fhi), "f"(flo))

// standard split: x = hi + lo
__device__ __forceinline__ void split_pair(float f0, float f1, uint32_t& uh, uint32_t& ul) {
    CVT_BF2(uh, f0, f1);
    float h0 = __uint_as_float(uh << 16);
    float h1 = __uint_as_float(uh & 0xffff0000u);
    CVT_BF2(ul, f0 - h0, f1 - h1);
}
// gram split: hi and 2*lo (exact doubling in bf16)
__device__ __forceinline__ void split_pair2(float f0, float f1, uint32_t& uh, uint32_t& ul) {
    CVT_BF2(uh, f0, f1);
    float h0 = __uint_as_float(uh << 16);
    float h1 = __uint_as_float(uh & 0xffff0000u);
    CVT_BF2(ul, 2.f * (f0 - h0), 2.f * (f1 - h1));
}
__device__ __forceinline__ void ldm_x4(uint32_t* r, uint32_t addr) {
    asm volatile("ldmatrix.sync.aligned.m8n8.x4.shared.b16 {%0,%1,%2,%3}, [%4];"
                 : "=r"(r[0]), "=r"(r[1]), "=r"(r[2]), "=r"(r[3]) : "r"(addr));
}
__device__ __forceinline__ void ldm_x4t(uint32_t* r, uint32_t addr) {
    asm volatile("ldmatrix.sync.aligned.m8n8.x4.trans.shared.b16 {%0,%1,%2,%3}, [%4];"
                 : "=r"(r[0]), "=r"(r[1]), "=r"(r[2]), "=r"(r[3]) : "r"(addr));
}
__device__ __forceinline__ void mma16816(float* d, const uint32_t* a, uint32_t b0, uint32_t b1) {
    asm volatile("mma.sync.aligned.m16n8k16.row.col.f32.bf16.bf16.f32 "
                 "{%0,%1,%2,%3}, {%4,%5,%6,%7}, {%8,%9}, {%0,%1,%2,%3};"
                 : "+f"(d[0]), "+f"(d[1]), "+f"(d[2]), "+f"(d[3])
                 : "r"(a[0]), "r"(a[1]), "r"(a[2]), "r"(a[3]), "r"(b0), "r"(b1));
}

// =============== Kernel 1: partial G = sym(Xh Xh^T + Xh (2Xl)^T) (pipelined) ===============
__global__ __launch_bounds__(NT)
void gram_kernel(const float* __restrict__ x)
{
    __shared__ __align__(16) __nv_bfloat16 sh[CH*LDB];
    __shared__ __align__(16) __nv_bfloat16 sl[CH*LDB];
    __shared__ float sp[NT];
    __shared__ float Ps[CH*LDC];          // P staging for in-CTA symmetrize

    const int b = blockIdx.x, s = blockIdx.y, tid = threadIdx.x;
    const float* xb = x + (size_t)b * CH * MDIM + (size_t)s * (MDIM / S1G);
    const uint32_t hb = smem_u32(sh), lb = smem_u32(sl);

    const int c = tid >> 2, q = tid & 3;
    const int w = tid >> 5, lane = tid & 31;
    const int r0 = (w >> 1) * 16, c0 = (w & 1) * 32;
    const int grp = lane >> 3, li = lane & 7;

    const uint32_t aoff = (uint32_t)(r0 + li + (grp & 1) * 8) * RB + (uint32_t)((grp >> 1) * 8) * 2;
    const uint32_t boff = (uint32_t)(c0 + li + (grp >> 1) * 8) * RB + (uint32_t)((grp & 1) * 8) * 2;

    float D[4][4] = {};
    float ssum = 0.f;

    float4 stage[4];
    {
        const float4* src = (const float4*)(xb + (size_t)c * MDIM);
#pragma unroll
        for (int j = 0; j < 4; ++j) stage[j] = src[q + 4 * j];
    }

    for (int t = 0; t < T1G; ++t) {
        // convert + store staged tile
#pragma unroll
        for (int j = 0; j < 4; ++j) {
            float4 v = stage[j];
            ssum += (v.x + v.y) + (v.z + v.w);
            uint32_t h0, l0, h1, l1;
            split_pair2(v.x, v.y, h0, l0);
            split_pair2(v.z, v.w, h1, l1);
            uint32_t off = (uint32_t)c * RB + (uint32_t)(q + 4 * j) * 8;
            STS64V2(hb + off, h0, h1);
            STS64V2(lb + off, l0, l1);
        }
        __syncthreads();

        // prefetch next tile (LDG latency overlaps MMA block below)
        if (t + 1 < T1G) {
            const float4* src = (const float4*)(xb + (size_t)c * MDIM + (t + 1) * 64);
#pragma unroll
            for (int j = 0; j < 4; ++j) stage[j] = src[q + 4 * j];
        }

#pragma unroll
        for (int kc = 0; kc < 4; ++kc) {
            const uint32_t ka = (uint32_t)kc * 32;
            uint32_t ah[4], bh0[4], bh1[4], bl0[4], bl1[4];
            ldm_x4(ah, hb + aoff + ka);
            ldm_x4(bh0, hb + boff + ka);
            ldm_x4(bh1, hb + boff + ka + 16 * RB);
            ldm_x4(bl0, lb + boff + ka);
            ldm_x4(bl1, lb + boff + ka + 16 * RB);
            mma16816(D[0], ah, bh0[0], bh0[1]);
            mma16816(D[1], ah, bh0[2], bh0[3]);
            mma16816(D[2], ah, bh1[0], bh1[1]);
            mma16816(D[3], ah, bh1[2], bh1[3]);
            mma16816(D[0], ah, bl0[0], bl0[1]);
            mma16816(D[1], ah, bl0[2], bl0[3]);
            mma16816(D[2], ah, bl1[0], bl1[1]);
            mma16816(D[3], ah, bl1[2], bl1[3]);
        }
        __syncthreads();
    }

    sp[tid] = ssum;
    __syncthreads();
    if (tid < CH)
        g_sums[(b * S1G + s) * CH + tid] =
            ((sp[tid * 4] + sp[tid * 4 + 1]) + sp[tid * 4 + 2]) + sp[tid * 4 + 3];

    // stage P into smem, symmetrize, write out
    {
        const int row = r0 + (lane >> 2);
        const int col = c0 + (lane & 3) * 2;
#pragma unroll
        for (int nb = 0; nb < 4; ++nb) {
            Ps[row * LDC + col + nb * 8]           = D[nb][0];
            Ps[row * LDC + col + nb * 8 + 1]       = D[nb][1];
            Ps[(row + 8) * LDC + col + nb * 8]     = D[nb][2];
            Ps[(row + 8) * LDC + col + nb * 8 + 1] = D[nb][3];
        }
    }
    __syncthreads();
    {
        float* gg = g_gram + (size_t)(b * S1G + s) * CH * CH;
        for (int idx = tid; idx < CH * CH; idx += NT) {
            int i = idx >> 6, j = idx & 63;
            gg[idx] = 0.5f * (Ps[i * LDC + j] + Ps[j * LDC + i]);
        }
    }
}

// =============== Kernel 2: reduce + shrinkage + Cholesky + inverse ===============
#define A_(i,j) covb[(63-(i))*LDC + (63-(j))]

__global__ __launch_bounds__(NT)
void chol_kernel()
{
    __shared__ float covb[CH*LDC];
    __shared__ float Wt[CH*LDW];
    __shared__ float s_mu[CH];
    __shared__ float s_invd[CH];
    __shared__ float s_w[8][2];
    __shared__ float s_bc[2];

    const int b = blockIdx.x, tid = threadIdx.x;

    if (tid < CH) {
        float m = 0.f;
#pragma unroll
        for (int s = 0; s < S1G; s++) m += g_sums[(b * S1G + s) * CH + tid];
        s_mu[tid] = m * (1.f / MDIM);
    }
    __syncthreads();

    for (int idx = tid; idx < CH * CH; idx += NT) {
        int i = idx >> 6, j = idx & 63;
        float g = 0.f;
#pragma unroll
        for (int p = 0; p < S1G; p++)
            g += g_gram[((size_t)(b * S1G + p)) * (CH * CH) + idx];
        covb[i * LDC + j] = g * (1.f / MDIM) - s_mu[i] * s_mu[j];
    }
    __syncthreads();

    float tr_p = 0.f, fr_p = 0.f;
    for (int idx = tid; idx < CH * CH; idx += NT) {
        int i = idx >> 6, j = idx & 63;
        float v = covb[i * LDC + j];
        fr_p += v * v;
        if (i == j) tr_p += v;
    }
#pragma unroll
    for (int o = 16; o; o >>= 1) {
        tr_p += __shfl_down_sync(0xffffffffu, tr_p, o);
        fr_p += __shfl_down_sync(0xffffffffu, fr_p, o);
    }
    if ((tid & 31) == 0) { s_w[tid >> 5][0] = tr_p; s_w[tid >> 5][1] = fr_p; }
    __syncthreads();
    if (tid == 0) {
        float tr = 0.f, st = 0.f;
#pragma unroll
        for (int w = 0; w < 8; w++) { tr += s_w[w][0]; st += s_w[w][1]; }
        const float n = (float)MDIM, p = (float)CH;
        float num = (n - 2.f) / n * st + tr * tr;
        float den = (n + 2.f) * (st - tr * tr / p);
        float rho = fminf(num / den, 1.f);
        s_bc[0] = rho;
        s_bc[1] = rho * tr / p;
    }
    __syncthreads();
    {
        const float rho = s_bc[0], dadd = s_bc[1];
        for (int idx = tid; idx < CH * CH; idx += NT) {
            int i = idx >> 6, j = idx & 63;
            float v = covb[i * LDC + j] * (1.f - rho);
            if (i == j) v += dadd;
            covb[i * LDC + j] = v;
        }
    }

    for (int k = 0; k < CH; ++k) {
        __syncthreads();
        if (tid == 0) {
            float d = A_(k, k);
            float sd = sqrtf(d);
            A_(k, k) = sd;
            s_bc[0] = 1.f / sd;
        }
        __syncthreads();
        if (tid > k && tid < CH) A_(tid, k) *= s_bc[0];
        __syncthreads();
        {
            int ii = tid & 63, g = tid >> 6;
            int i = k + 1 + ii;
            if (i < CH) {
                float aik = A_(i, k);
                for (int j = k + 1 + g; j <= i; j += 4)
                    A_(i, j) -= aik * A_(j, k);
            }
        }
    }
    __syncthreads();

    if (tid < CH) s_invd[tid] = 1.f / covb[tid * LDC + tid];
    for (int idx = tid; idx < CH * LDW; idx += NT) Wt[idx] = 0.f;
    __syncthreads();

    if (tid < CH) {
        const int j = tid;
        Wt[j * LDW + j] = s_invd[j];
        for (int i = j - 1; i >= 0; --i) {
            float a = 0.f;
            for (int k = i + 1; k <= j; ++k)
                a += covb[i * LDC + k] * Wt[j * LDW + k];
            Wt[j * LDW + i] = -a * s_invd[i];
        }
    }
    __syncthreads();

    // store W row-major: g_W[c][d] = W[c][d] = Wt[d][c]
    for (int idx = tid; idx < CH * CH; idx += NT) {
        int cc = idx >> 6, d = idx & 63;
        g_W[(size_t)b * CH * CH + idx] = Wt[d * LDW + cc];
    }
    if (tid < CH) g_mu[b * CH + tid] = s_mu[tid];
}

// =============== Kernel 3: Z = W (x - mu) via HMMA bf16 split (pipelined) ===============
__global__ __launch_bounds__(NT)
void apply_kernel(const float* __restrict__ x, float* __restrict__ z)
{
    __shared__ __align__(16) __nv_bfloat16 wh[CH*LDB];
    __shared__ __align__(16) __nv_bfloat16 wl[CH*LDB];
    __shared__ __align__(16) __nv_bfloat16 xh[CH*LDB];
    __shared__ __align__(16) __nv_bfloat16 xl[CH*LDB];

    const int b = blockIdx.x, s = blockIdx.y, tid = threadIdx.x;
    const float* xb = x + (size_t)b * CH * MDIM;
    float*       zb = z + (size_t)b * CH * MDIM;
    const uint32_t whb = smem_u32(wh), wlb = smem_u32(wl);
    const uint32_t xhb = smem_u32(xh), xlb = smem_u32(xl);

    const int c = tid >> 2, q = tid & 3;
    const int w = tid >> 5, lane = tid & 31;
    const int r0 = (w >> 1) * 16, m0 = (w & 1) * 32;
    const int grp = lane >> 3, li = lane & 7;

    const float mu_c = g_mu[b * CH + c];

    // load + split W (row-major [c][d])
    {
        const float4* wsrc = (const float4*)(g_W + (size_t)b * CH * CH + (size_t)c * CH);
#pragma unroll
        for (int j = 0; j < 4; ++j) {
            float4 v = wsrc[q + 4 * j];
            uint32_t h0, l0, h1, l1;
            split_pair(v.x, v.y, h0, l0);
            split_pair(v.z, v.w, h1, l1);
            uint32_t off = (uint32_t)c * RB + (uint32_t)(q + 4 * j) * 8;
            STS64V2(whb + off, h0, h1);
            STS64V2(wlb + off, l0, l1);
        }
    }

    // prefetch first x tile while W settles
    float4 stage[4];
    {
        const float4* src = (const float4*)(xb + (size_t)c * MDIM + s * (T2A * 64));
#pragma unroll
        for (int j = 0; j < 4; ++j) stage[j] = src[q + 4 * j];
    }
    __syncthreads();

    // preload W fragments (reused for all tiles)
    uint32_t wah[4][4], wal[4][4];
    {
        const uint32_t aoff = (uint32_t)(r0 + li + (grp & 1) * 8) * RB + (uint32_t)((grp >> 1) * 8) * 2;
#pragma unroll
        for (int kc = 0; kc < 4; ++kc) {
            ldm_x4(wah[kc], whb + aoff + kc * 32);
            ldm_x4(wal[kc], wlb + aoff + kc * 32);
        }
    }

    const uint32_t boff = (uint32_t)(li + (grp & 1) * 8) * RB + (uint32_t)(m0 + (grp >> 1) * 8) * 2;

    for (int t = 0; t < T2A; ++t) {
        const int mg0 = s * (T2A * 64) + t * 64;
#pragma unroll
        for (int j = 0; j < 4; ++j) {
            float4 v = stage[j];
            v.x -= mu_c; v.y -= mu_c; v.z -= mu_c; v.w -= mu_c;
            uint32_t h0, l0, h1, l1;
            split_pair(v.x, v.y, h0, l0);
            split_pair(v.z, v.w, h1, l1);
            uint32_t off = (uint32_t)c * RB + (uint32_t)(q + 4 * j) * 8;
            STS64V2(xhb + off, h0, h1);
            STS64V2(xlb + off, l0, l1);
        }
        __syncthreads();

        if (t + 1 < T2A) {
            const float4* src = (const float4*)(xb + (size_t)c * MDIM + mg0 + 64);
#pragma unroll
            for (int j = 0; j < 4; ++j) stage[j] = src[q + 4 * j];
        }

        float D[4][4] = {};
#pragma unroll
        for (int kc = 0; kc < 4; ++kc) {
            const uint32_t kb = (uint32_t)(kc * 16) * RB;
            uint32_t bh0[4], bh1[4], bl0[4], bl1[4];
            ldm_x4t(bh0, xhb + boff + kb);
            ldm_x4t(bh1, xhb + boff + kb + 32);
            ldm_x4t(bl0, xlb + boff + kb);
            ldm_x4t(bl1, xlb + boff + kb + 32);
            mma16816(D[0], wah[kc], bh0[0], bh0[1]);
            mma16816(D[0], wah[kc], bl0[0], bl0[1]);
            mma16816(D[0], wal[kc], bh0[0], bh0[1]);
            mma16816(D[1], wah[kc], bh0[2], bh0[3]);
            mma16816(D[1], wah[kc], bl0[2], bl0[3]);
            mma16816(D[1], wal[kc], bh0[2], bh0[3]);
            mma16816(D[2], wah[kc], bh1[0], bh1[1]);
            mma16816(D[2], wah[kc], bl1[0], bl1[1]);
            mma16816(D[2], wal[kc], bh1[0], bh1[1]);
            mma16816(D[3], wah[kc], bh1[2], bh1[3]);
            mma16816(D[3], wah[kc], bl1[2], bl1[3]);
            mma16816(D[3], wal[kc], bh1[2], bh1[3]);
        }

        const int row = r0 + (lane >> 2);
        const int mg = mg0 + m0 + (lane & 3) * 2;
#pragma unroll
        for (int nb = 0; nb < 4; ++nb) {
            *(float2*)(zb + (size_t)row * MDIM + mg + nb * 8)       = make_float2(D[nb][0], D[nb][1]);
            *(float2*)(zb + (size_t)(row + 8) * MDIM + mg + nb * 8) = make_float2(D[nb][2], D[nb][3]);
        }
        __syncthreads();
    }
}

extern "C" void kernel_launch(void* const* d_in, const int* in_sizes, int n_in,
                              void* d_out, int out_size)
{
    const float* x = (const float*)d_in[0];
    float* z = (float*)d_out;

    gram_kernel<<<dim3(BATCH, S1G), NT>>>(x);
    chol_kernel<<<BATCH, NT>>>();
    apply_kernel<<<dim3(BATCH, S2A), NT>>>(x, z);
}

// round 15
// speedup vs baseline: 1.1414x; 1.0227x over previous
#include <cuda_runtime.h>
#include <cuda_bf16.h>
#include <cstdint>
#include <math.h>

#define BATCH 256
#define CH    64
#define MDIM  4096
#define NT    256
#define S1G   4
#define T1G   ((MDIM/S1G)/64)   // 16 tiles per gram CTA
#define S2A   8
#define T2A   ((MDIM/S2A)/64)   // 8 tiles per apply CTA
#define LDB   72                // bf16 elements per smem row
#define RB    144               // row bytes
#define LDC   65
#define LDW   65

__device__ float g_gram[(size_t)BATCH*S1G*CH*CH];
__device__ float g_sums[BATCH*S1G*CH];
__device__ float g_W[(size_t)BATCH*CH*CH];
__device__ float g_mu[BATCH*CH];

__device__ __forceinline__ uint32_t smem_u32(const void* p) {
    uint32_t a;
    asm("{ .reg .u64 t; cvta.to.shared.u64 t, %1; cvt.u32.u64 %0, t; }" : "=r"(a) : "l"(p));
    return a;
}
#define STS64V2(a,r0,r1) asm volatile("st.shared.v2.b32 [%0], {%1,%2};" :: "r"(a), "r"(r0), "r"(r1) : "memory")
#define CVT_BF2(res,flo,fhi) asm("cvt.rn.satfinite.bf16x2.f32 %0, %1, %2;" : "=r"(res) : "f"(fhi), "f"(flo))

// standard split: x = hi + lo
__device__ __forceinline__ void split_pair(float f0, float f1, uint32_t& uh, uint32_t& ul) {
    CVT_BF2(uh, f0, f1);
    float h0 = __uint_as_float(uh << 16);
    float h1 = __uint_as_float(uh & 0xffff0000u);
    CVT_BF2(ul, f0 - h0, f1 - h1);
}
// gram split: hi and 2*lo (exact doubling in bf16)
__device__ __forceinline__ void split_pair2(float f0, float f1, uint32_t& uh, uint32_t& ul) {
    CVT_BF2(uh, f0, f1);
    float h0 = __uint_as_float(uh << 16);
    float h1 = __uint_as_float(uh & 0xffff0000u);
    CVT_BF2(ul, 2.f * (f0 - h0), 2.f * (f1 - h1));
}
__device__ __forceinline__ void ldm_x4(uint32_t* r, uint32_t addr) {
    asm volatile("ldmatrix.sync.aligned.m8n8.x4.shared.b16 {%0,%1,%2,%3}, [%4];"
                 : "=r"(r[0]), "=r"(r[1]), "=r"(r[2]), "=r"(r[3]) : "r"(addr));
}
__device__ __forceinline__ void ldm_x4t(uint32_t* r, uint32_t addr) {
    asm volatile("ldmatrix.sync.aligned.m8n8.x4.trans.shared.b16 {%0,%1,%2,%3}, [%4];"
                 : "=r"(r[0]), "=r"(r[1]), "=r"(r[2]), "=r"(r[3]) : "r"(addr));
}
__device__ __forceinline__ void mma16816(float* d, const uint32_t* a, uint32_t b0, uint32_t b1) {
    asm volatile("mma.sync.aligned.m16n8k16.row.col.f32.bf16.bf16.f32 "
                 "{%0,%1,%2,%3}, {%4,%5,%6,%7}, {%8,%9}, {%0,%1,%2,%3};"
                 : "+f"(d[0]), "+f"(d[1]), "+f"(d[2]), "+f"(d[3])
                 : "r"(a[0]), "r"(a[1]), "r"(a[2]), "r"(a[3]), "r"(b0), "r"(b1));
}

// =============== Kernel 1: partial G = sym(Xh Xh^T + Xh (2Xl)^T) (pipelined) ===============
// warp tile 32 rows x 16 cols: 4 ldm per kc (2 A-hi + B-hi + B-lo) instead of 5
__global__ __launch_bounds__(NT)
void gram_kernel(const float* __restrict__ x)
{
    __shared__ __align__(16) __nv_bfloat16 sh[CH*LDB];
    __shared__ __align__(16) __nv_bfloat16 sl[CH*LDB];
    __shared__ float sp[NT];
    __shared__ float Ps[CH*LDC];          // P staging for in-CTA symmetrize

    const int b = blockIdx.x, s = blockIdx.y, tid = threadIdx.x;
    const float* xb = x + (size_t)b * CH * MDIM + (size_t)s * (MDIM / S1G);
    const uint32_t hb = smem_u32(sh), lb = smem_u32(sl);

    const int c = tid >> 2, q = tid & 3;
    const int w = tid >> 5, lane = tid & 31;
    const int r0 = (w >> 2) * 32, c0 = (w & 3) * 16;
    const int grp = lane >> 3, li = lane & 7;

    const uint32_t aoff = (uint32_t)(r0 + li + (grp & 1) * 8) * RB + (uint32_t)((grp >> 1) * 8) * 2;
    const uint32_t boff = (uint32_t)(c0 + li + (grp >> 1) * 8) * RB + (uint32_t)((grp & 1) * 8) * 2;

    float D[4][4] = {};          // [mi*2+ni]: rows r0+16*mi, cols c0+8*ni
    float ssum = 0.f;

    float4 stage[4];
    {
        const float4* src = (const float4*)(xb + (size_t)c * MDIM);
#pragma unroll
        for (int j = 0; j < 4; ++j) stage[j] = src[q + 4 * j];
    }

    for (int t = 0; t < T1G; ++t) {
        // convert + store staged tile
#pragma unroll
        for (int j = 0; j < 4; ++j) {
            float4 v = stage[j];
            ssum += (v.x + v.y) + (v.z + v.w);
            uint32_t h0, l0, h1, l1;
            split_pair2(v.x, v.y, h0, l0);
            split_pair2(v.z, v.w, h1, l1);
            uint32_t off = (uint32_t)c * RB + (uint32_t)(q + 4 * j) * 8;
            STS64V2(hb + off, h0, h1);
            STS64V2(lb + off, l0, l1);
        }
        __syncthreads();

        // prefetch next tile (LDG latency overlaps MMA block below)
        if (t + 1 < T1G) {
            const float4* src = (const float4*)(xb + (size_t)c * MDIM + (t + 1) * 64);
#pragma unroll
            for (int j = 0; j < 4; ++j) stage[j] = src[q + 4 * j];
        }

#pragma unroll
        for (int kc = 0; kc < 4; ++kc) {
            const uint32_t ka = (uint32_t)kc * 32;
            uint32_t ah0[4], ah1[4], bh[4], bl[4];
            ldm_x4(ah0, hb + aoff + ka);
            ldm_x4(ah1, hb + aoff + 16 * RB + ka);
            ldm_x4(bh,  hb + boff + ka);
            ldm_x4(bl,  lb + boff + ka);
            mma16816(D[0], ah0, bh[0], bh[1]);
            mma16816(D[1], ah0, bh[2], bh[3]);
            mma16816(D[2], ah1, bh[0], bh[1]);
            mma16816(D[3], ah1, bh[2], bh[3]);
            mma16816(D[0], ah0, bl[0], bl[1]);
            mma16816(D[1], ah0, bl[2], bl[3]);
            mma16816(D[2], ah1, bl[0], bl[1]);
            mma16816(D[3], ah1, bl[2], bl[3]);
        }
        __syncthreads();
    }

    sp[tid] = ssum;
    __syncthreads();
    if (tid < CH)
        g_sums[(b * S1G + s) * CH + tid] =
            ((sp[tid * 4] + sp[tid * 4 + 1]) + sp[tid * 4 + 2]) + sp[tid * 4 + 3];

    // stage P into smem, symmetrize, write out
    {
        const int lrow = lane >> 2, lcol = (lane & 3) * 2;
#pragma unroll
        for (int mi = 0; mi < 2; ++mi)
#pragma unroll
            for (int ni = 0; ni < 2; ++ni) {
                const float* d = D[mi * 2 + ni];
                int rr = r0 + 16 * mi + lrow;
                int cc = c0 + 8 * ni + lcol;
                Ps[rr * LDC + cc]           = d[0];
                Ps[rr * LDC + cc + 1]       = d[1];
                Ps[(rr + 8) * LDC + cc]     = d[2];
                Ps[(rr + 8) * LDC + cc + 1] = d[3];
            }
    }
    __syncthreads();
    {
        float* gg = g_gram + (size_t)(b * S1G + s) * CH * CH;
        for (int idx = tid; idx < CH * CH; idx += NT) {
            int i = idx >> 6, j = idx & 63;
            gg[idx] = 0.5f * (Ps[i * LDC + j] + Ps[j * LDC + i]);
        }
    }
}

// =============== Kernel 2: reduce + shrinkage + Cholesky + inverse ===============
#define A_(i,j) covb[(63-(i))*LDC + (63-(j))]

__global__ __launch_bounds__(NT)
void chol_kernel()
{
    __shared__ float covb[CH*LDC];
    __shared__ float Wt[CH*LDW];
    __shared__ float s_mu[CH];
    __shared__ float s_invd[CH];
    __shared__ float s_w[8][2];
    __shared__ float s_bc[2];

    const int b = blockIdx.x, tid = threadIdx.x;

    if (tid < CH) {
        float m = 0.f;
#pragma unroll
        for (int s = 0; s < S1G; s++) m += g_sums[(b * S1G + s) * CH + tid];
        s_mu[tid] = m * (1.f / MDIM);
    }
    __syncthreads();

    for (int idx = tid; idx < CH * CH; idx += NT) {
        int i = idx >> 6, j = idx & 63;
        float g = 0.f;
#pragma unroll
        for (int p = 0; p < S1G; p++)
            g += g_gram[((size_t)(b * S1G + p)) * (CH * CH) + idx];
        covb[i * LDC + j] = g * (1.f / MDIM) - s_mu[i] * s_mu[j];
    }
    __syncthreads();

    float tr_p = 0.f, fr_p = 0.f;
    for (int idx = tid; idx < CH * CH; idx += NT) {
        int i = idx >> 6, j = idx & 63;
        float v = covb[i * LDC + j];
        fr_p += v * v;
        if (i == j) tr_p += v;
    }
#pragma unroll
    for (int o = 16; o; o >>= 1) {
        tr_p += __shfl_down_sync(0xffffffffu, tr_p, o);
        fr_p += __shfl_down_sync(0xffffffffu, fr_p, o);
    }
    if ((tid & 31) == 0) { s_w[tid >> 5][0] = tr_p; s_w[tid >> 5][1] = fr_p; }
    __syncthreads();
    if (tid == 0) {
        float tr = 0.f, st = 0.f;
#pragma unroll
        for (int w = 0; w < 8; w++) { tr += s_w[w][0]; st += s_w[w][1]; }
        const float n = (float)MDIM, p = (float)CH;
        float num = (n - 2.f) / n * st + tr * tr;
        float den = (n + 2.f) * (st - tr * tr / p);
        float rho = fminf(num / den, 1.f);
        s_bc[0] = rho;
        s_bc[1] = rho * tr / p;
    }
    __syncthreads();
    {
        const float rho = s_bc[0], dadd = s_bc[1];
        for (int idx = tid; idx < CH * CH; idx += NT) {
            int i = idx >> 6, j = idx & 63;
            float v = covb[i * LDC + j] * (1.f - rho);
            if (i == j) v += dadd;
            covb[i * LDC + j] = v;
        }
    }

    for (int k = 0; k < CH; ++k) {
        __syncthreads();
        if (tid == 0) {
            float d = A_(k, k);
            float sd = sqrtf(d);
            A_(k, k) = sd;
            s_bc[0] = 1.f / sd;
        }
        __syncthreads();
        if (tid > k && tid < CH) A_(tid, k) *= s_bc[0];
        __syncthreads();
        {
            int ii = tid & 63, g = tid >> 6;
            int i = k + 1 + ii;
            if (i < CH) {
                float aik = A_(i, k);
                for (int j = k + 1 + g; j <= i; j += 4)
                    A_(i, j) -= aik * A_(j, k);
            }
        }
    }
    __syncthreads();

    if (tid < CH) s_invd[tid] = 1.f / covb[tid * LDC + tid];
    for (int idx = tid; idx < CH * LDW; idx += NT) Wt[idx] = 0.f;
    __syncthreads();

    if (tid < CH) {
        const int j = tid;
        Wt[j * LDW + j] = s_invd[j];
        for (int i = j - 1; i >= 0; --i) {
            float a = 0.f;
            for (int k = i + 1; k <= j; ++k)
                a += covb[i * LDC + k] * Wt[j * LDW + k];
            Wt[j * LDW + i] = -a * s_invd[i];
        }
    }
    __syncthreads();

    // store W row-major: g_W[c][d] = W[c][d] = Wt[d][c]
    for (int idx = tid; idx < CH * CH; idx += NT) {
        int cc = idx >> 6, d = idx & 63;
        g_W[(size_t)b * CH * CH + idx] = Wt[d * LDW + cc];
    }
    if (tid < CH) g_mu[b * CH + tid] = s_mu[tid];
}

// =============== Kernel 3: Z = W (x - mu) via HMMA bf16 split (pipelined) ===============
__global__ __launch_bounds__(NT)
void apply_kernel(const float* __restrict__ x, float* __restrict__ z)
{
    __shared__ __align__(16) __nv_bfloat16 wh[CH*LDB];
    __shared__ __align__(16) __nv_bfloat16 wl[CH*LDB];
    __shared__ __align__(16) __nv_bfloat16 xh[CH*LDB];
    __shared__ __align__(16) __nv_bfloat16 xl[CH*LDB];

    const int b = blockIdx.x, s = blockIdx.y, tid = threadIdx.x;
    const float* xb = x + (size_t)b * CH * MDIM;
    float*       zb = z + (size_t)b * CH * MDIM;
    const uint32_t whb = smem_u32(wh), wlb = smem_u32(wl);
    const uint32_t xhb = smem_u32(xh), xlb = smem_u32(xl);

    const int c = tid >> 2, q = tid & 3;
    const int w = tid >> 5, lane = tid & 31;
    const int r0 = (w >> 1) * 16, m0 = (w & 1) * 32;
    const int grp = lane >> 3, li = lane & 7;

    const float mu_c = g_mu[b * CH + c];

    // load + split W (row-major [c][d])
    {
        const float4* wsrc = (const float4*)(g_W + (size_t)b * CH * CH + (size_t)c * CH);
#pragma unroll
        for (int j = 0; j < 4; ++j) {
            float4 v = wsrc[q + 4 * j];
            uint32_t h0, l0, h1, l1;
            split_pair(v.x, v.y, h0, l0);
            split_pair(v.z, v.w, h1, l1);
            uint32_t off = (uint32_t)c * RB + (uint32_t)(q + 4 * j) * 8;
            STS64V2(whb + off, h0, h1);
            STS64V2(wlb + off, l0, l1);
        }
    }

    // prefetch first x tile while W settles
    float4 stage[4];
    {
        const float4* src = (const float4*)(xb + (size_t)c * MDIM + s * (T2A * 64));
#pragma unroll
        for (int j = 0; j < 4; ++j) stage[j] = src[q + 4 * j];
    }
    __syncthreads();

    // preload W fragments (reused for all tiles)
    uint32_t wah[4][4], wal[4][4];
    {
        const uint32_t aoff = (uint32_t)(r0 + li + (grp & 1) * 8) * RB + (uint32_t)((grp >> 1) * 8) * 2;
#pragma unroll
        for (int kc = 0; kc < 4; ++kc) {
            ldm_x4(wah[kc], whb + aoff + kc * 32);
            ldm_x4(wal[kc], wlb + aoff + kc * 32);
        }
    }

    const uint32_t boff = (uint32_t)(li + (grp & 1) * 8) * RB + (uint32_t)(m0 + (grp >> 1) * 8) * 2;

    for (int t = 0; t < T2A; ++t) {
        const int mg0 = s * (T2A * 64) + t * 64;
#pragma unroll
        for (int j = 0; j < 4; ++j) {
            float4 v = stage[j];
            v.x -= mu_c; v.y -= mu_c; v.z -= mu_c; v.w -= mu_c;
            uint32_t h0, l0, h1, l1;
            split_pair(v.x, v.y, h0, l0);
            split_pair(v.z, v.w, h1, l1);
            uint32_t off = (uint32_t)c * RB + (uint32_t)(q + 4 * j) * 8;
            STS64V2(xhb + off, h0, h1);
            STS64V2(xlb + off, l0, l1);
        }
        __syncthreads();

        if (t + 1 < T2A) {
            const float4* src = (const float4*)(xb + (size_t)c * MDIM + mg0 + 64);
#pragma unroll
            for (int j = 0; j < 4; ++j) stage[j] = src[q + 4 * j];
        }

        float D[4][4] = {};
#pragma unroll
        for (int kc = 0; kc < 4; ++kc) {
            const uint32_t kb = (uint32_t)(kc * 16) * RB;
            uint32_t bh0[4], bh1[4], bl0[4], bl1[4];
            ldm_x4t(bh0, xhb + boff + kb);
            ldm_x4t(bh1, xhb + boff + kb + 32);
            ldm_x4t(bl0, xlb + boff + kb);
            ldm_x4t(bl1, xlb + boff + kb + 32);
            mma16816(D[0], wah[kc], bh0[0], bh0[1]);
            mma16816(D[0], wah[kc], bl0[0], bl0[1]);
            mma16816(D[0], wal[kc], bh0[0], bh0[1]);
            mma16816(D[1], wah[kc], bh0[2], bh0[3]);
            mma16816(D[1], wah[kc], bl0[2], bl0[3]);
            mma16816(D[1], wal[kc], bh0[2], bh0[3]);
            mma16816(D[2], wah[kc], bh1[0], bh1[1]);
            mma16816(D[2], wah[kc], bl1[0], bl1[1]);
            mma16816(D[2], wal[kc], bh1[0], bh1[1]);
            mma16816(D[3], wah[kc], bh1[2], bh1[3]);
            mma16816(D[3], wah[kc], bl1[2], bl1[3]);
            mma16816(D[3], wal[kc], bh1[2], bh1[3]);
        }

        const int row = r0 + (lane >> 2);
        const int mg = mg0 + m0 + (lane & 3) * 2;
#pragma unroll
        for (int nb = 0; nb < 4; ++nb) {
            *(float2*)(zb + (size_t)row * MDIM + mg + nb * 8)       = make_float2(D[nb][0], D[nb][1]);
            *(float2*)(zb + (size_t)(row + 8) * MDIM + mg + nb * 8) = make_float2(D[nb][2], D[nb][3]);
        }
        __syncthreads();
    }
}

extern "C" void kernel_launch(void* const* d_in, const int* in_sizes, int n_in,
                              void* d_out, int out_size)
{
    const float* x = (const float*)d_in[0];
    float* z = (float*)d_out;

    gram_kernel<<<dim3(BATCH, S1G), NT>>>(x);
    chol_kernel<<<BATCH, NT>>>();
    apply_kernel<<<dim3(BATCH, S2A), NT>>>(x, z);
}